// round 1
// baseline (speedup 1.0000x reference)
#include <cuda_runtime.h>
#include <cstdint>

// dilate_tensor: input (16,128,128,128) f32 NHWC -> output (16,256,256,128)
// out[n, 2*ih+1, 2*iw+1, c] = in[n, ih, iw, c]; all other elements zero.
//
// C=128 floats is contiguous and unchanged by the dilation, so each output
// (n, oh, ow) pixel is a 512-byte run that is either a straight copy of the
// corresponding input pixel (oh odd && ow odd) or all zeros.
//
// One thread per float4 of output. All dims are powers of two -> shift/mask
// indexing only. Fully coalesced 16B loads and stores.

#define N_   16
#define H_   128
#define W_   128
#define C_   128
#define OH_  (2 * H_)
#define OW_  (2 * W_)
#define C4_  (C_ / 4)              // 32 float4 per pixel

// Total output float4 count = 16 * 256 * 256 * 32 = 2^25
#define TOTAL_OUT_F4 (N_ * OH_ * OW_ * C4_)

__global__ __launch_bounds__(256) void dilate_kernel(const float4* __restrict__ in,
                                                     float4* __restrict__ out)
{
    const uint32_t idx = blockIdx.x * 256u + threadIdx.x;   // < 2^25, exact grid

    // Decompose (power-of-two dims):
    //   c4 = idx & 31
    //   ow = (idx >> 5)  & 255
    //   oh = (idx >> 13) & 255
    //   n  =  idx >> 21
    const uint32_t c4 = idx & (C4_ - 1);
    const uint32_t ow = (idx >> 5) & (OW_ - 1);
    const uint32_t oh = (idx >> 13) & (OH_ - 1);
    const uint32_t n  = idx >> 21;

    float4 v = make_float4(0.f, 0.f, 0.f, 0.f);
    if ((oh & ow & 1u) != 0u) {
        // input float4 index: ((n*128 + oh/2)*128 + ow/2)*32 + c4
        const uint32_t iidx = (n << 19) | ((oh >> 1) << 12) | ((ow >> 1) << 5) | c4;
        v = __ldg(&in[iidx]);
    }
    out[idx] = v;
}

extern "C" void kernel_launch(void* const* d_in, const int* in_sizes, int n_in,
                              void* d_out, int out_size)
{
    (void)in_sizes; (void)n_in; (void)out_size;
    const float4* in  = (const float4*)d_in[0];
    float4*       out = (float4*)d_out;

    const int threads = 256;
    const int blocks  = TOTAL_OUT_F4 / threads;   // 131072, exact
    dilate_kernel<<<blocks, threads>>>(in, out);
}